// round 15
// baseline (speedup 1.0000x reference)
#include <cuda_runtime.h>
#include <cuda_bf16.h>
#include <math.h>
#include <stdint.h>

// Model dims
#define SEQ    2048
#define DIM    1024
#define NHEAD  16
#define DH     64
#define NLAYER 2
#define NEXP   8
#define FFI    512
#define SFI    1024
#define VOCAB  32000
#define NCB    (VOCAB / 128)

#define BK 64
#define NSTAGE 3
#define BSTRIDE 72
#define STAGE_BYTES (128 * BSTRIDE * 2)        // 18432
#define GEMM_SMEM (2 * NSTAGE * STAGE_BYTES)   // 110592

#define CONV_GRID 1184

#define QSCALE 0.1803368801111137f  // 0.125 * log2(e)

// flash-attn smem layout (bytes)
#define FA_Q     0
#define FA_QSZ   (128 * 72 * 2)
#define FA_K     (FA_Q + FA_QSZ)
#define FA_KSZ   (128 * 72 * 2)
#define FA_V     (FA_K + 2 * FA_KSZ)
#define FA_VSZ   (64 * 136 * 2)
#define FA_SMEM  (FA_V + 2 * FA_VSZ)    // 90112

// layer weight scratch layout (bf16 elems)
#define WDD   ((size_t)DIM * DIM)
#define O_QKV 0
#define O_WO  (3 * WDD)
#define O_GU  (4 * WDD)
#define O_DN  (O_GU + (size_t)NEXP * 2 * FFI * DIM)
#define O_SH  (O_DN + (size_t)NEXP * FFI * DIM)
#define O_SD  (O_SH + (size_t)2 * SFI * DIM)
#define WL_TOTAL (O_SD + (size_t)SFI * DIM)

// ---------------- static scratch ----------------
__device__ float g_h[SEQ * DIM];
__device__ __nv_bfloat16 g_xb[SEQ * DIM];
__device__ __nv_bfloat16 g_qkvb[SEQ * 3 * DIM];
__device__ __nv_bfloat16 g_qbh[(size_t)NHEAD * SEQ * DH];
__device__ __nv_bfloat16 g_kbh[(size_t)NHEAD * SEQ * DH];
__device__ __nv_bfloat16 g_vth[(size_t)NHEAD * DH * SEQ];
__device__ __nv_bfloat16 g_ob[SEQ * DIM];
__device__ __nv_bfloat16 g_ygb[(size_t)NEXP * SEQ * DIM];   // MoE down outputs (bf16)
__device__ __nv_bfloat16 g_actb[(size_t)NEXP * SEQ * FFI];
__device__ __nv_bfloat16 g_xg[(size_t)NEXP * SEQ * DIM];
__device__ __nv_bfloat16 g_gsb[SEQ * SFI];
__device__ __nv_bfloat16 g_wl0[WL_TOTAL];
__device__ __nv_bfloat16 g_wl1[WL_TOTAL];
__device__ __nv_bfloat16 g_wbL[(size_t)VOCAB * DIM];
__device__ float2 g_part[(size_t)SEQ * NCB];
__device__ int   g_cnt[NEXP];
__device__ int2  g_topi[SEQ];
__device__ int2  g_pos[SEQ];
__device__ float2 g_topw[SEQ];

// ---------------- helpers ----------------
__device__ __forceinline__ uint32_t cvt_bf16x2(float lo, float hi) {
    uint32_t r;
    asm("cvt.rn.bf16x2.f32 %0, %1, %2;" : "=r"(r) : "f"(hi), "f"(lo));
    return r;
}
__device__ __forceinline__ void ldsm4(uint32_t &r0, uint32_t &r1, uint32_t &r2, uint32_t &r3,
                                      uint32_t addr) {
    asm volatile("ldmatrix.sync.aligned.m8n8.x4.shared.b16 {%0,%1,%2,%3}, [%4];"
                 : "=r"(r0), "=r"(r1), "=r"(r2), "=r"(r3) : "r"(addr));
}
__device__ __forceinline__ void mma16816(float* c, const uint32_t* a, const uint32_t* b) {
    asm volatile(
        "mma.sync.aligned.m16n8k16.row.col.f32.bf16.bf16.f32 "
        "{%0,%1,%2,%3}, {%4,%5,%6,%7}, {%8,%9}, {%0,%1,%2,%3};"
        : "+f"(c[0]), "+f"(c[1]), "+f"(c[2]), "+f"(c[3])
        : "r"(a[0]), "r"(a[1]), "r"(a[2]), "r"(a[3]), "r"(b[0]), "r"(b[1]));
}
__device__ __forceinline__ void cp_async16(uint32_t dst, const void* src) {
    asm volatile("cp.async.cg.shared.global [%0], [%1], 16;" :: "r"(dst), "l"(src));
}
__device__ __forceinline__ void cp_commit() { asm volatile("cp.async.commit_group;"); }
template<int W> __device__ __forceinline__ void cp_wait() {
    asm volatile("cp.async.wait_group %0;" :: "n"(W));
}

// ---------------- 128x128 GEMM mainloop, BK=64, 3-stage ----------------
__device__ __forceinline__ void gemm128_mainloop(
    const __nv_bfloat16* __restrict__ A, const __nv_bfloat16* __restrict__ B,
    int K, int lda, int ldb, float acc[2][8][4])
{
    extern __shared__ __align__(16) __nv_bfloat16 smem[];
    const int tid = threadIdx.x;
    const int lane = tid & 31;
    const int wid = tid >> 5;
    const int warp_m = wid & 3;
    const int warp_n = wid >> 2;
    const int g = lane >> 3, lr = lane & 7;

    const uint32_t As_base = (uint32_t)__cvta_generic_to_shared(smem);
    const uint32_t Bs_base = As_base + NSTAGE * STAGE_BYTES;
    const int ntiles = K >> 6;

    auto issue = [&](int t, int s) {
        const __nv_bfloat16* Ag = A + t * BK;
        const __nv_bfloat16* Bg = B + t * BK;
        const uint32_t a_s = As_base + s * STAGE_BYTES;
        const uint32_t b_s = Bs_base + s * STAGE_BYTES;
#pragma unroll
        for (int i = 0; i < 4; i++) {
            int id = i * 256 + tid;
            int r = id >> 3;
            int c = (id & 7) * 8;
            cp_async16(a_s + (r * BSTRIDE + c) * 2, Ag + (size_t)r * lda + c);
            cp_async16(b_s + (r * BSTRIDE + c) * 2, Bg + (size_t)r * ldb + c);
        }
    };

#pragma unroll
    for (int s = 0; s < NSTAGE - 1; s++) {
        if (s < ntiles) issue(s, s);
        cp_commit();
    }

#pragma unroll
    for (int mt = 0; mt < 2; mt++)
#pragma unroll
        for (int nt = 0; nt < 8; nt++)
#pragma unroll
            for (int i = 0; i < 4; i++) acc[mt][nt][i] = 0.f;

    int s = 0;
    for (int t = 0; t < ntiles; t++) {
        cp_wait<NSTAGE - 2>();
        __syncthreads();

        const uint32_t a_base = As_base + s * STAGE_BYTES;
        const uint32_t b_base = Bs_base + s * STAGE_BYTES;

#pragma unroll
        for (int ks = 0; ks < 4; ks++) {
            uint32_t a[2][4];
#pragma unroll
            for (int mt = 0; mt < 2; mt++) {
                int row = warp_m * 32 + mt * 16 + (g & 1) * 8 + lr;
                int col = ks * 16 + (g >> 1) * 8;
                ldsm4(a[mt][0], a[mt][1], a[mt][2], a[mt][3],
                      a_base + (uint32_t)(row * BSTRIDE + col) * 2);
            }
            uint32_t b[8][2];
#pragma unroll
            for (int np = 0; np < 4; np++) {
                int row = warp_n * 64 + np * 16 + (g >> 1) * 8 + lr;
                int col = ks * 16 + (g & 1) * 8;
                uint32_t r0, r1, r2, r3;
                ldsm4(r0, r1, r2, r3, b_base + (uint32_t)(row * BSTRIDE + col) * 2);
                b[2 * np][0] = r0; b[2 * np][1] = r1;
                b[2 * np + 1][0] = r2; b[2 * np + 1][1] = r3;
            }
#pragma unroll
            for (int mt = 0; mt < 2; mt++)
#pragma unroll
                for (int nt = 0; nt < 8; nt++)
                    mma16816(acc[mt][nt], a[mt], b[nt]);
        }

        int nt2 = t + NSTAGE - 1;
        if (nt2 < ntiles) {
            int s2 = nt2 % NSTAGE;
            issue(nt2, s2);
        }
        cp_commit();
        s = (s + 1 == NSTAGE) ? 0 : s + 1;
    }
}

template<bool ACC>
__device__ __forceinline__ void epilogue_store(float* __restrict__ C, int ldc,
                                               float acc[2][8][4])
{
    const int tid = threadIdx.x;
    const int lane = tid & 31;
    const int wid = tid >> 5;
    const int warp_m = wid & 3;
    const int warp_n = wid >> 2;
    const int r0c = lane >> 2;
    const int cc  = (lane & 3) * 2;
#pragma unroll
    for (int mt = 0; mt < 2; mt++) {
        int rbase = warp_m * 32 + mt * 16 + r0c;
#pragma unroll
        for (int nt = 0; nt < 8; nt++) {
            int col = warp_n * 64 + nt * 8 + cc;
            size_t i00 = (size_t)rbase * ldc + col;
            size_t i10 = (size_t)(rbase + 8) * ldc + col;
            if (ACC) {
                C[i00]     += acc[mt][nt][0]; C[i00 + 1] += acc[mt][nt][1];
                C[i10]     += acc[mt][nt][2]; C[i10 + 1] += acc[mt][nt][3];
            } else {
                C[i00]     = acc[mt][nt][0]; C[i00 + 1] = acc[mt][nt][1];
                C[i10]     = acc[mt][nt][2]; C[i10 + 1] = acc[mt][nt][3];
            }
        }
    }
}

__device__ __forceinline__ void epilogue_store_bf16(__nv_bfloat16* __restrict__ C, int ldc,
                                                    float acc[2][8][4])
{
    const int tid = threadIdx.x;
    const int lane = tid & 31;
    const int wid = tid >> 5;
    const int warp_m = wid & 3;
    const int warp_n = wid >> 2;
    const int r0c = lane >> 2;
    const int cc  = (lane & 3) * 2;
#pragma unroll
    for (int mt = 0; mt < 2; mt++) {
        int rbase = warp_m * 32 + mt * 16 + r0c;
#pragma unroll
        for (int nt = 0; nt < 8; nt++) {
            int col = warp_n * 64 + nt * 8 + cc;
            *(uint32_t*)(C + (size_t)rbase * ldc + col) =
                cvt_bf16x2(acc[mt][nt][0], acc[mt][nt][1]);
            *(uint32_t*)(C + (size_t)(rbase + 8) * ldc + col) =
                cvt_bf16x2(acc[mt][nt][2], acc[mt][nt][3]);
        }
    }
}

__device__ __forceinline__ void epilogue_act(__nv_bfloat16* __restrict__ O, int ldo,
                                             float acc[2][8][4])
{
    const int tid = threadIdx.x;
    const int lane = tid & 31;
    const int wid = tid >> 5;
    const int warp_m = wid & 3;
    const int warp_n = wid >> 2;
    const int r0c = lane >> 2;
    const int cp0 = lane & 3;
#pragma unroll
    for (int mt = 0; mt < 2; mt++) {
        int rbase = warp_m * 32 + mt * 16 + r0c;
#pragma unroll
        for (int nt = 0; nt < 8; nt++) {
            int cp = warp_n * 32 + nt * 4 + cp0;
            float g0 = acc[mt][nt][0], u0 = acc[mt][nt][1];
            float g1 = acc[mt][nt][2], u1 = acc[mt][nt][3];
            float s0 = 1.f / (1.f + expf(-g0));
            float s1 = 1.f / (1.f + expf(-g1));
            O[(size_t)rbase * ldo + cp]       = __float2bfloat16(g0 * s0 * u0);
            O[(size_t)(rbase + 8) * ldo + cp] = __float2bfloat16(g1 * s1 * u1);
        }
    }
}

template<bool ACC>
__global__ void __launch_bounds__(256, 2) bf16_gemm_kernel(
    const __nv_bfloat16* __restrict__ A, const __nv_bfloat16* __restrict__ B,
    float* __restrict__ C, int K, int lda, int ldb, int ldc)
{
    A += (size_t)blockIdx.y * 128 * lda;
    B += (size_t)blockIdx.x * 128 * ldb;
    C += (size_t)blockIdx.y * 128 * ldc + blockIdx.x * 128;
    float acc[2][8][4];
    gemm128_mainloop(A, B, K, lda, ldb, acc);
    epilogue_store<ACC>(C, ldc, acc);
}

__global__ void __launch_bounds__(256, 2) bf16_gemm_bf16out(
    const __nv_bfloat16* __restrict__ A, const __nv_bfloat16* __restrict__ B,
    __nv_bfloat16* __restrict__ C, int K, int lda, int ldb, int ldc)
{
    A += (size_t)blockIdx.y * 128 * lda;
    B += (size_t)blockIdx.x * 128 * ldb;
    C += (size_t)blockIdx.y * 128 * ldc + blockIdx.x * 128;
    float acc[2][8][4];
    gemm128_mainloop(A, B, K, lda, ldb, acc);
    epilogue_store_bf16(C, ldc, acc);
}

__global__ void __launch_bounds__(256, 2) gemm_act_kernel(
    const __nv_bfloat16* __restrict__ A, const __nv_bfloat16* __restrict__ B,
    __nv_bfloat16* __restrict__ O, int K)
{
    A += (size_t)blockIdx.y * 128 * K;
    B += (size_t)blockIdx.x * 128 * K;
    O += (size_t)blockIdx.y * 128 * SFI + blockIdx.x * 64;
    float acc[2][8][4];
    gemm128_mainloop(A, B, K, K, K, acc);
    epilogue_act(O, SFI, acc);
}

__global__ void __launch_bounds__(256, 2) moe_gemm_act_kernel(
    const __nv_bfloat16* __restrict__ A, const __nv_bfloat16* __restrict__ B,
    __nv_bfloat16* __restrict__ O, const int* __restrict__ cnt)
{
    const int e = blockIdx.y >> 4;
    const int rb = blockIdx.y & 15;
    if (rb * 128 >= cnt[e]) return;
    A += ((size_t)e * SEQ + rb * 128) * DIM;
    B += (size_t)e * (2 * FFI) * DIM + (size_t)blockIdx.x * 128 * DIM;
    O += ((size_t)e * SEQ + rb * 128) * FFI + blockIdx.x * 64;
    float acc[2][8][4];
    gemm128_mainloop(A, B, DIM, DIM, DIM, acc);
    epilogue_act(O, FFI, acc);
}

// MoE down GEMM, bf16 output
__global__ void __launch_bounds__(256, 2) moe_gemm_kernel(
    const __nv_bfloat16* __restrict__ A, const __nv_bfloat16* __restrict__ B,
    __nv_bfloat16* __restrict__ C, const int* __restrict__ cnt, int K, int N)
{
    const int e = blockIdx.y >> 4;
    const int rb = blockIdx.y & 15;
    if (rb * 128 >= cnt[e]) return;
    A += ((size_t)e * SEQ + rb * 128) * K;
    B += (size_t)e * N * K + (size_t)blockIdx.x * 128 * K;
    C += ((size_t)e * SEQ + rb * 128) * N + blockIdx.x * 128;
    float acc[2][8][4];
    gemm128_mainloop(A, B, K, K, K, acc);
    epilogue_store_bf16(C, N, acc);
}

__global__ void __launch_bounds__(256, 2) lmhead_gemm_loss(
    const __nv_bfloat16* __restrict__ A, const __nv_bfloat16* __restrict__ B,
    float2* __restrict__ part, int K)
{
    const int bx = blockIdx.x;
    A += (size_t)blockIdx.y * 128 * K;
    B += (size_t)bx * 128 * K;
    float acc[2][8][4];
    gemm128_mainloop(A, B, K, K, K, acc);

    const int tid = threadIdx.x;
    const int lane = tid & 31;
    const int wid = tid >> 5;
    const int warp_m = wid & 3;
    const int warp_n = wid >> 2;

    __shared__ float sm_m[2][128], sm_s[2][128];

#pragma unroll
    for (int mt = 0; mt < 2; mt++) {
#pragma unroll
        for (int half = 0; half < 2; half++) {
            float m = -1e30f;
#pragma unroll
            for (int nt = 0; nt < 8; nt++)
                m = fmaxf(m, fmaxf(acc[mt][nt][2 * half], acc[mt][nt][2 * half + 1]));
            m = fmaxf(m, __shfl_xor_sync(0xffffffffu, m, 1));
            m = fmaxf(m, __shfl_xor_sync(0xffffffffu, m, 2));
            float s = 0.f;
#pragma unroll
            for (int nt = 0; nt < 8; nt++)
                s += expf(acc[mt][nt][2 * half] - m) + expf(acc[mt][nt][2 * half + 1] - m);
            s += __shfl_xor_sync(0xffffffffu, s, 1);
            s += __shfl_xor_sync(0xffffffffu, s, 2);
            if ((lane & 3) == 0) {
                int row_local = warp_m * 32 + mt * 16 + half * 8 + (lane >> 2);
                sm_m[warp_n][row_local] = m;
                sm_s[warp_n][row_local] = s;
            }
        }
    }
    __syncthreads();

    if (tid < 128) {
        float m1 = sm_m[0][tid], s1 = sm_s[0][tid];
        float m2 = sm_m[1][tid], s2 = sm_s[1][tid];
        float nm = fmaxf(m1, m2);
        float ns = s1 * expf(m1 - nm) + s2 * expf(m2 - nm);
        int row = blockIdx.y * 128 + tid;
        part[(size_t)row * NCB + bx] = make_float2(nm, ns);
    }
}

__global__ void loss_reduce(const float2* __restrict__ part,
                            const __nv_bfloat16* __restrict__ xb,
                            const __nv_bfloat16* __restrict__ wb,
                            const int* __restrict__ tgt, float* __restrict__ out)
{
    int row = blockIdx.x;
    int tid = threadIdx.x;

    float m = -1e30f, s = 0.f;
    for (int j = tid; j < NCB; j += 256) {
        float2 p = part[(size_t)row * NCB + j];
        float nm = fmaxf(m, p.x);
        s = s * expf(m - nm) + p.y * expf(p.x - nm);
        m = nm;
    }

    __shared__ float ms[256], ss[256], ds[256];
    ms[tid] = m; ss[tid] = s;
    __syncthreads();
    for (int st = 128; st > 0; st >>= 1) {
        if (tid < st) {
            float m1 = ms[tid], m2 = ms[tid + st];
            float nm = fmaxf(m1, m2);
            ss[tid] = ss[tid] * expf(m1 - nm) + ss[tid + st] * expf(m2 - nm);
            ms[tid] = nm;
        }
        __syncthreads();
    }

    int lab = tgt[row];
    int slab = (lab == -100) ? 0 : lab;
    const __nv_bfloat16* xr = xb + (size_t)row * DIM;
    const __nv_bfloat16* wr = wb + (size_t)slab * DIM;
    float d = 0.f;
    for (int i = tid; i < DIM; i += 256)
        d += __bfloat162float(xr[i]) * __bfloat162float(wr[i]);
    ds[tid] = d;
    __syncthreads();
    for (int st = 128; st > 0; st >>= 1) {
        if (tid < st) ds[tid] += ds[tid + st];
        __syncthreads();
    }

    if (tid == 0 && lab != -100) {
        float lse = ms[0] + logf(ss[0]);
        atomicAdd(out, lse - ds[0]);
    }
}

// ---------------- weight conversion (grid-stride) ----------------
__global__ void convert_w(const float* __restrict__ w, __nv_bfloat16* __restrict__ wb,
                          size_t n4)
{
    const float4* w4 = (const float4*)w;
    uint2* o2 = (uint2*)wb;
    size_t stride = (size_t)gridDim.x * 256;
    for (size_t i = (size_t)blockIdx.x * 256 + threadIdx.x; i < n4; i += stride * 4) {
        float4 v[4];
        bool ok[4];
#pragma unroll
        for (int k = 0; k < 4; k++) {
            size_t j = i + (size_t)k * stride;
            ok[k] = j < n4;
            if (ok[k]) v[k] = w4[j];
        }
#pragma unroll
        for (int k = 0; k < 4; k++) if (ok[k]) {
            uint2 pk;
            pk.x = cvt_bf16x2(v[k].x, v[k].y);
            pk.y = cvt_bf16x2(v[k].z, v[k].w);
            o2[i + (size_t)k * stride] = pk;
        }
    }
}

__global__ void convert_pair(const float* __restrict__ a, const float* __restrict__ b,
                             __nv_bfloat16* __restrict__ wb, size_t n4, int log2r2)
{
    uint2* o2 = (uint2*)wb;
    size_t stride = (size_t)gridDim.x * 256;
    for (size_t i = (size_t)blockIdx.x * 256 + threadIdx.x; i < n4; i += stride * 4) {
        float4 v[4];
        bool ok[4];
#pragma unroll
        for (int k = 0; k < 4; k++) {
            size_t j = i + (size_t)k * stride;
            ok[k] = j < n4;
            if (ok[k]) {
                int k4 = (int)(j & 255);
                size_t n = j >> 8;
                size_t e = n >> log2r2;
                int r = (int)(n & ((1u << log2r2) - 1));
                const float* src = ((r & 1) ? b : a)
                    + ((e << (log2r2 - 1)) + (r >> 1)) * (size_t)DIM + k4 * 4;
                v[k] = *(const float4*)src;
            }
        }
#pragma unroll
        for (int k = 0; k < 4; k++) if (ok[k]) {
            uint2 pk;
            pk.x = cvt_bf16x2(v[k].x, v[k].y);
            pk.y = cvt_bf16x2(v[k].z, v[k].w);
            o2[i + (size_t)k * stride] = pk;
        }
    }
}

// ---------------- rope (bf16 in) -> bf16 per-head Q/K ----------------
__global__ void rope_bf16_kernel(const __nv_bfloat16* __restrict__ qkv,
                                 __nv_bfloat16* __restrict__ qb,
                                 __nv_bfloat16* __restrict__ kb)
{
    int s = blockIdx.x;
    int tid = threadIdx.x;
    int h = tid >> 5, i = tid & 31;
    float freq = powf(10000.f, -(float)(2 * i) / 64.f);
    float ang = (float)s * freq;
    float sn, cs;
    sincosf(ang, &sn, &cs);
    size_t src = (size_t)s * (3 * DIM) + h * DH + i;
    float q1 = __bfloat162float(qkv[src]), q2 = __bfloat162float(qkv[src + 32]);
    size_t dst = ((size_t)h * SEQ + s) * DH + i;
    qb[dst]      = __float2bfloat16((q1 * cs - q2 * sn) * QSCALE);
    qb[dst + 32] = __float2bfloat16((q2 * cs + q1 * sn) * QSCALE);
    float k1 = __bfloat162float(qkv[src + DIM]), k2 = __bfloat162float(qkv[src + DIM + 32]);
    kb[dst]      = __float2bfloat16(k1 * cs - k2 * sn);
    kb[dst + 32] = __float2bfloat16(k2 * cs + k1 * sn);
}

__global__ void vtrans_kernel(const __nv_bfloat16* __restrict__ v,
                              __nv_bfloat16* __restrict__ vt)
{
    __shared__ __nv_bfloat16 tile[32][34];
    int s0 = blockIdx.x * 32, d0 = blockIdx.y * 32;
    int tx = threadIdx.x, ty = threadIdx.y;
#pragma unroll
    for (int i = 0; i < 4; i++) {
        int row = ty + i * 8;
        tile[row][tx] = v[(size_t)(s0 + row) * (3 * DIM) + 2 * DIM + d0 + tx];
    }
    __syncthreads();
#pragma unroll
    for (int i = 0; i < 4; i++) {
        int row = ty + i * 8;
        vt[(size_t)(d0 + row) * SEQ + s0 + tx] = tile[tx][row];
    }
}

// ---------------- flash attention ----------------
__global__ void __launch_bounds__(256, 1) flash_attn2_kernel(
    const __nv_bfloat16* __restrict__ qb, const __nv_bfloat16* __restrict__ kb,
    const __nv_bfloat16* __restrict__ vt, __nv_bfloat16* __restrict__ ob)
{
    extern __shared__ __align__(16) char fasm[];
    const int qblk = blockIdx.x;
    const int head = blockIdx.y;
    const int q0 = qblk * 128;

    const int tid = threadIdx.x;
    const int lane = tid & 31;
    const int wid = tid >> 5;
    const int g = lane >> 3, lr = lane & 7;
    const int r0 = wid * 16;

    const uint32_t smb = (uint32_t)__cvta_generic_to_shared(fasm);
    const uint32_t Qs = smb + FA_Q;
    const uint32_t Ks = smb + FA_K;
    const uint32_t Vs = smb + FA_V;

    const __nv_bfloat16* Qg = qb + ((size_t)head * SEQ + q0) * DH;
    const __nv_bfloat16* Kg = kb + (size_t)head * SEQ * DH;
    const __nv_bfloat16* Vg = vt + (size_t)head * DH * SEQ;

#pragma unroll
    for (int i = 0; i < 4; i++) {
        int id = i * 256 + tid;
        int r = id >> 3;
        int c = id & 7;
        cp_async16(Qs + (uint32_t)(r * 144 + c * 16), Qg + (size_t)r * DH + c * 8);
    }
    cp_commit();

    auto issueKV = [&](int kblk, int buf) {
        const int kk0 = kblk * 128;
        const uint32_t kdst = Ks + buf * FA_KSZ;
        const uint32_t vdst = Vs + buf * FA_VSZ;
#pragma unroll
        for (int i = 0; i < 4; i++) {
            int id = i * 256 + tid;
            int r = id >> 3;
            int c = id & 7;
            cp_async16(kdst + (uint32_t)(r * 144 + c * 16),
                       Kg + (size_t)(kk0 + r) * DH + c * 8);
        }
#pragma unroll
        for (int i = 0; i < 4; i++) {
            int id = i * 256 + tid;
            int d = id >> 4;
            int c = id & 15;
            cp_async16(vdst + (uint32_t)(d * 272 + c * 16),
                       Vg + (size_t)d * SEQ + kk0 + c * 8);
        }
    };

    issueKV(0, 0);
    cp_commit();
    cp_wait<0>();
    __syncthreads();

    uint32_t qa[4][4];
#pragma unroll
    for (int kt = 0; kt < 4; kt++) {
        int row = r0 + (g & 1) * 8 + lr;
        int col = kt * 16 + (g >> 1) * 8;
        ldsm4(qa[kt][0], qa[kt][1], qa[kt][2], qa[kt][3],
              Qs + (uint32_t)(row * 72 + col) * 2);
    }

    float acc_o[8][4];
#pragma unroll
    for (int nt = 0; nt < 8; nt++)
#pragma unroll
        for (int i = 0; i < 4; i++) acc_o[nt][i] = 0.f;

    float mA = -1e30f, mB = -1e30f, lA = 0.f, lB = 0.f;
    const int rA = q0 + r0 + (lane >> 2);
    const int rB = rA + 8;

    for (int kblk = 0; kblk <= qblk; kblk++) {
        const int kk0 = kblk * 128;
        const int buf = kblk & 1;

        if (kblk > 0) {
            cp_wait<0>();
            __syncthreads();
        }
        if (kblk < qblk) {
            issueKV(kblk + 1, buf ^ 1);
            cp_commit();
        }

        const uint32_t kbase = Ks + buf * FA_KSZ;
        const uint32_t vbase = Vs + buf * FA_VSZ;

        float sacc[16][4];
#pragma unroll
        for (int nt = 0; nt < 16; nt++)
#pragma unroll
            for (int i = 0; i < 4; i++) sacc[nt][i] = 0.f;

#pragma unroll
        for (int kt = 0; kt < 4; kt++) {
#pragma unroll
            for (int np = 0; np < 8; np++) {
                int row = np * 16 + (g >> 1) * 8 + lr;
                int col = kt * 16 + (g & 1) * 8;
                uint32_t b0, b1, b2, b3;
                ldsm4(b0, b1, b2, b3, kbase + (uint32_t)(row * 72 + col) * 2);
                uint32_t bb0[2] = {b0, b1}, bb1[2] = {b2, b3};
                mma16816(sacc[2 * np],     qa[kt], bb0);
                mma16816(sacc[2 * np + 1], qa[kt], bb1);
            }
        }

        if (kblk == qblk) {
#pragma unroll
            for (int nt = 0; nt < 16; nt++) {
                int cb = kk0 + nt * 8 + 2 * (lane & 3);
                if (cb     > rA) sacc[nt][0] = -1e30f;
                if (cb + 1 > rA) sacc[nt][1] = -1e30f;
                if (cb     > rB) sacc[nt][2] = -1e30f;
                if (cb + 1 > rB) sacc[nt][3] = -1e30f;
            }
        }

        float cmA = -1e30f, cmB = -1e30f;
#pragma unroll
        for (int nt = 0; nt < 16; nt++) {
            cmA = fmaxf(cmA, fmaxf(sacc[nt][0], sacc[nt][1]));
            cmB = fmaxf(cmB, fmaxf(sacc[nt][2], sacc[nt][3]));
        }
        cmA = fmaxf(cmA, __shfl_xor_sync(0xffffffffu, cmA, 1));
        cmA = fmaxf(cmA, __shfl_xor_sync(0xffffffffu, cmA, 2));
        cmB = fmaxf(cmB, __shfl_xor_sync(0xffffffffu, cmB, 1));
        cmB = fmaxf(cmB, __shfl_xor_sync(0xffffffffu, cmB, 2));

        float nmA = fmaxf(mA, cmA), nmB = fmaxf(mB, cmB);
        float scA = exp2f(mA - nmA), scB = exp2f(mB - nmB);
        mA = nmA; mB = nmB;

        uint32_t pA[16], pB[16];
        float sA = 0.f, sB = 0.f;
#pragma unroll
        for (int nt = 0; nt < 16; nt++) {
            float p0 = exp2f(sacc[nt][0] - mA);
            float p1 = exp2f(sacc[nt][1] - mA);
            float p2 = exp2f(sacc[nt][2] - mB);
            float p3 = exp2f(sacc[nt][3] - mB);
            sA += p0 + p1; sB += p2 + p3;
            pA[nt] = cvt_bf16x2(p0, p1);
            pB[nt] = cvt_bf16x2(p2, p3);
        }
        lA = lA * scA + sA;
        lB = lB * scB + sB;
#pragma unroll
        for (int nt = 0; nt < 8; nt++) {
            acc_o[nt][0] *= scA; acc_o[nt][1] *= scA;
            acc_o[nt][2] *= scB; acc_o[nt][3] *= scB;
        }

#pragma unroll
        for (int kt2 = 0; kt2 < 8; kt2++) {
            uint32_t a[4] = { pA[2 * kt2], pB[2 * kt2], pA[2 * kt2 + 1], pB[2 * kt2 + 1] };
#pragma unroll
            for (int np2 = 0; np2 < 4; np2++) {
                int row = np2 * 16 + (g >> 1) * 8 + lr;
                int col = kt2 * 16 + (g & 1) * 8;
                uint32_t b0, b1, b2, b3;
                ldsm4(b0, b1, b2, b3, vbase + (uint32_t)(row * 136 + col) * 2);
                uint32_t bb0[2] = {b0, b1}, bb1[2] = {b2, b3};
                mma16816(acc_o[2 * np2],     a, bb0);
                mma16816(acc_o[2 * np2 + 1], a, bb1);
            }
        }
    }

    lA += __shfl_xor_sync(0xffffffffu, lA, 1);
    lA += __shfl_xor_sync(0xffffffffu, lA, 2);
    lB += __shfl_xor_sync(0xffffffffu, lB, 1);
    lB += __shfl_xor_sync(0xffffffffu, lB, 2);
    float iA = 1.f / lA, iB = 1.f / lB;

#pragma unroll
    for (int nt = 0; nt < 8; nt++) {
        int col = head * DH + nt * 8 + 2 * (lane & 3);
        uint32_t p0 = cvt_bf16x2(acc_o[nt][0] * iA, acc_o[nt][1] * iA);
        uint32_t p1 = cvt_bf16x2(acc_o[nt][2] * iB, acc_o[nt][3] * iB);
        *(uint32_t*)(ob + (size_t)rA * DIM + col) = p0;
        *(uint32_t*)(ob + (size_t)rB * DIM + col) = p1;
    }
}

// ---------------- small kernels ----------------
__global__ void embed_gather(const int* __restrict__ tok, const float* __restrict__ emb,
                             float* __restrict__ h)
{
    int s = blockIdx.x;
    int t = tok[s];
    const float* e = emb + (size_t)t * DIM;
    for (int d = threadIdx.x; d < DIM; d += blockDim.x)
        h[(size_t)s * DIM + d] = e[d];
}

__global__ void rmsnorm_kernel(const float* __restrict__ x, const float* __restrict__ w,
                               __nv_bfloat16* __restrict__ o)
{
    int row = blockIdx.x;
    const float* xr = x + (size_t)row * DIM;
    __shared__ float red[256];
    int tid = threadIdx.x;
    float s = 0.f;
    for (int d = tid; d < DIM; d += 256) { float v = xr[d]; s += v * v; }
    red[tid] = s; __syncthreads();
    for (int st = 128; st > 0; st >>= 1) {
        if (tid < st) red[tid] += red[tid + st];
        __syncthreads();
    }
    float rs = rsqrtf(red[0] / (float)DIM + 1e-6f);
    for (int d = tid; d < DIM; d += 256)
        o[(size_t)row * DIM + d] = __float2bfloat16(xr[d] * rs * w[d]);
}

__global__ void gate_topk(const __nv_bfloat16* __restrict__ x, const float* __restrict__ gw,
                          int2* __restrict__ topi, float2* __restrict__ topw)
{
    int t = blockIdx.x;
    int tid = threadIdx.x;
    int e = tid >> 5, lane = tid & 31;
    const __nv_bfloat16* xr = x + (size_t)t * DIM;
    const float* wr = gw + (size_t)e * DIM;
    float s = 0.f;
    for (int d = lane; d < DIM; d += 32) s += __bfloat162float(xr[d]) * wr[d];
    for (int o = 16; o; o >>= 1) s += __shfl_down_sync(0xffffffffu, s, o);
    __shared__ float lg[NEXP];
    if (lane == 0) lg[e] = s;
    __syncthreads();
    if (tid == 0) {
        float m = -1e30f;
        for (int i = 0; i < NEXP; i++) m = fmaxf(m, lg[i]);
        float p[NEXP]; float sum = 0.f;
        for (int i = 0; i < NEXP; i++) { p[i] = expf(lg[i] - m); sum += p[i]; }
        float inv = 1.f / sum;
        for (int i = 0; i < NEXP; i++) p[i] *= inv;
        int i0 = 0;
        for (int i = 1; i < NEXP; i++) if (p[i] > p[i0]) i0 = i;
        int i1 = -1;
        for (int i = 0; i < NEXP; i++) {
            if (i == i0) continue;
            if (i1 < 0 || p[i] > p[i1]) i1 = i;
        }
        topi[t] = make_int2(i0, i1);
        topw[t] = make_float2(p[i0], p[i1]);
    }
}

__global__ void zero_counts(int* cnt)
{
    if (threadIdx.x < NEXP) cnt[threadIdx.x] = 0;
}

__global__ void gather_rows(const __nv_bfloat16* __restrict__ xb, __nv_bfloat16* __restrict__ xg,
                            const int2* __restrict__ topi, int2* __restrict__ pos,
                            int* __restrict__ cnt)
{
    int t = blockIdx.x;
    __shared__ int sp[2];
    int2 ti = topi[t];
    if (threadIdx.x == 0) {
        sp[0] = atomicAdd(&cnt[ti.x], 1);
        sp[1] = atomicAdd(&cnt[ti.y], 1);
    }
    __syncthreads();
    const uint32_t* src = (const uint32_t*)(xb + (size_t)t * DIM);
    uint32_t* d0 = (uint32_t*)(xg + ((size_t)ti.x * SEQ + sp[0]) * DIM);
    uint32_t* d1 = (uint32_t*)(xg + ((size_t)ti.y * SEQ + sp[1]) * DIM);
    for (int i = threadIdx.x; i < DIM / 2; i += 256) {
        uint32_t v = src[i];
        d0[i] = v; d1[i] = v;
    }
    if (threadIdx.x == 0) pos[t] = make_int2(sp[0], sp[1]);
}

// scatter from bf16 yg
__global__ void scatter_add(float* __restrict__ h, const __nv_bfloat16* __restrict__ yg,
                            const int2* __restrict__ topi, const int2* __restrict__ pos,
                            const float2* __restrict__ topw)
{
    int t = blockIdx.x;
    int2 ti = topi[t];
    int2 ps = pos[t];
    float2 w = topw[t];
    const __nv_bfloat16* y0 = yg + ((size_t)ti.x * SEQ + ps.x) * DIM;
    const __nv_bfloat16* y1 = yg + ((size_t)ti.y * SEQ + ps.y) * DIM;
    float* hr = h + (size_t)t * DIM;
    for (int d = threadIdx.x; d < DIM; d += 256)
        hr[d] += w.x * __bfloat162float(y0[d]) + w.y * __bfloat162float(y1[d]);
}

__global__ void zero_scalar(float* p)
{
    if (threadIdx.x == 0 && blockIdx.x == 0) p[0] = 0.f;
}

// ---------------- host ----------------
static void gemm_acc(const __nv_bfloat16* A, const __nv_bfloat16* B, float* C,
                     int M, int N, int K, int lda, int ldb, int ldc)
{
    bf16_gemm_kernel<true><<<dim3(N / 128, M / 128), 256, GEMM_SMEM>>>(A, B, C, K, lda, ldb, ldc);
}
static void conv_w_s(cudaStream_t s, const float* w, __nv_bfloat16* wb, size_t nelem)
{
    convert_w<<<CONV_GRID, 256, 0, s>>>(w, wb, nelem / 4);
}

extern "C" void kernel_launch(void* const* d_in, const int* in_sizes, int n_in,
                              void* d_out, int out_size)
{
    (void)in_sizes; (void)n_in; (void)out_size;
    const int*   src       = (const int*)d_in[0];
    const int*   tgt       = (const int*)d_in[1];
    const float* embed     = (const float*)d_in[2];
    const float* Wq        = (const float*)d_in[3];
    const float* Wk        = (const float*)d_in[4];
    const float* Wv        = (const float*)d_in[5];
    const float* Wo        = (const float*)d_in[6];
    const float* ln1       = (const float*)d_in[7];
    const float* ln2       = (const float*)d_in[8];
    const float* gate_w    = (const float*)d_in[9];
    const float* gate_proj = (const float*)d_in[10];
    const float* up_proj   = (const float*)d_in[11];
    const float* down_proj = (const float*)d_in[12];
    const float* sg        = (const float*)d_in[13];
    const float* su        = (const float*)d_in[14];
    const float* sd        = (const float*)d_in[15];
    const float* final_ln  = (const float*)d_in[16];
    const float* lm_head   = (const float*)d_in[17];
    float* out = (float*)d_out;

    static cudaStream_t sC = nullptr;
    static cudaEvent_t evFork = nullptr, evA[NLAYER], evM[NLAYER], evLM = nullptr;
    if (!sC) {
        cudaStreamCreateWithFlags(&sC, cudaStreamNonBlocking);
        cudaEventCreateWithFlags(&evFork, cudaEventDisableTiming);
        for (int l = 0; l < NLAYER; l++) {
            cudaEventCreateWithFlags(&evA[l], cudaEventDisableTiming);
            cudaEventCreateWithFlags(&evM[l], cudaEventDisableTiming);
        }
        cudaEventCreateWithFlags(&evLM, cudaEventDisableTiming);

        cudaFuncSetAttribute(bf16_gemm_kernel<false>, cudaFuncAttributeMaxDynamicSharedMemorySize, GEMM_SMEM);
        cudaFuncSetAttribute(bf16_gemm_kernel<true>,  cudaFuncAttributeMaxDynamicSharedMemorySize, GEMM_SMEM);
        cudaFuncSetAttribute(bf16_gemm_bf16out,       cudaFuncAttributeMaxDynamicSharedMemorySize, GEMM_SMEM);
        cudaFuncSetAttribute(moe_gemm_kernel,         cudaFuncAttributeMaxDynamicSharedMemorySize, GEMM_SMEM);
        cudaFuncSetAttribute(moe_gemm_act_kernel,     cudaFuncAttributeMaxDynamicSharedMemorySize, GEMM_SMEM);
        cudaFuncSetAttribute(gemm_act_kernel,         cudaFuncAttributeMaxDynamicSharedMemorySize, GEMM_SMEM);
        cudaFuncSetAttribute(lmhead_gemm_loss,        cudaFuncAttributeMaxDynamicSharedMemorySize, GEMM_SMEM);
        cudaFuncSetAttribute(flash_attn2_kernel,      cudaFuncAttributeMaxDynamicSharedMemorySize, FA_SMEM);
    }

    float *h;
    __nv_bfloat16 *xb, *qkvb, *qbh, *kbh, *vth, *ob, *ygb, *actb, *xg, *gsb, *wbL;
    __nv_bfloat16 *wl[NLAYER];
    float2 *partb;
    int *cnt; int2 *topi, *pos; float2 *topw;
    cudaGetSymbolAddress((void**)&h,     g_h);
    cudaGetSymbolAddress((void**)&xb,    g_xb);
    cudaGetSymbolAddress((void**)&qkvb,  g_qkvb);
    cudaGetSymbolAddress((void**)&qbh,   g_qbh);
    cudaGetSymbolAddress((void**)&kbh,   g_kbh);
    cudaGetSymbolAddress((void**)&vth,   g_vth);
    cudaGetSymbolAddress((void**)&ob,    g_ob);
    cudaGetSymbolAddress((void**)&ygb,   g_ygb);
    cudaGetSymbolAddress((void**)&actb,  g_actb);
    cudaGetSymbolAddress((void**)&xg,    g_xg);
    cudaGetSymbolAddress((void**)&gsb,   g_gsb);
    cudaGetSymbolAddress((void**)&wl[0], g_wl0);
    cudaGetSymbolAddress((void**)&wl[1], g_wl1);
    cudaGetSymbolAddress((void**)&wbL,   g_wbL);
    cudaGetSymbolAddress((void**)&partb, g_part);
    cudaGetSymbolAddress((void**)&cnt,   g_cnt);
    cudaGetSymbolAddress((void**)&topi,  g_topi);
    cudaGetSymbolAddress((void**)&pos,   g_pos);
    cudaGetSymbolAddress((void**)&topw,  g_topw);

    const size_t DD = WDD;
    const size_t EID = (size_t)NEXP * FFI * DIM;
    const size_t SD = (size_t)SFI * DIM;

    // ---- fork: weight conversions on side stream, fine-grained events ----
    cudaEventRecord(evFork, 0);
    cudaStreamWaitEvent(sC, evFork, 0);
    for (int l = 0; l < NLAYER; l++) {
        __nv_bfloat16* wl_ = wl[l];
        // attention weights first
        conv_w_s(sC, Wq + l * DD, wl_ + O_QKV,          DD);
        conv_w_s(sC, Wk + l * DD, wl_ + O_QKV + DD,     DD);
        conv_w_s(sC, Wv + l * DD, wl_ + O_QKV + 2 * DD, DD);
        conv_w_s(sC, Wo + l * DD, wl_ + O_WO, DD);
        cudaEventRecord(evA[l], sC);
        // MoE + shared weights
        convert_pair<<<CONV_GRID, 256, 0, sC>>>(gate_proj + l * EID, up_proj + l * EID,
                                                wl_ + O_GU, 2 * EID / 4, 10);
        conv_w_s(sC, down_proj + l * EID, wl_ + O_DN, EID);
        convert_pair<<<CONV_GRID, 256, 0, sC>>>(sg + l * SD, su + l * SD,
                                                wl_ + O_SH, 2 * SD / 4, 11);
        conv_w_s(sC, sd + l * SD, wl_ + O_SD, SD);
        cudaEventRecord(evM[l], sC);
    }
    conv_w_s(sC, lm_head, wbL, (size_t)VOCAB * DIM);
    cudaEventRecord(evLM, sC);

    // ---- main stream compute ----
    embed_gather<<<SEQ, 256>>>(src, embed, h);

    for (int l = 0; l < NLAYER; l++) {
        __nv_bfloat16* w = wl[l];
        rmsnorm_kernel<<<SEQ, 256>>>(h, ln1 + (size_t)l * DIM, xb);
        cudaStreamWaitEvent(0, evA[l], 0);

        bf16_gemm_bf16out<<<dim3((3 * DIM) / 128, SEQ / 128), 256, GEMM_SMEM>>>(
            xb, w + O_QKV, qkvb, DIM, DIM, DIM, 3 * DIM);
        rope_bf16_kernel<<<SEQ, NHEAD * 32>>>(qkvb, qbh, kbh);
        vtrans_kernel<<<dim3(SEQ / 32, DIM / 32), dim3(32, 8)>>>(qkvb, vth);

        flash_attn2_kernel<<<dim3(SEQ / 128, NHEAD), 256, FA_SMEM>>>(qbh, kbh, vth, ob);

        gemm_acc(ob, w + O_WO, h, SEQ, DIM, DIM, DIM, DIM, DIM);

        // ---- MoE (sparse top-2, fused act) ----
        rmsnorm_kernel<<<SEQ, 256>>>(h, ln2 + (size_t)l * DIM, xb);
        gate_topk<<<SEQ, 256>>>(xb, gate_w + (size_t)l * NEXP * DIM, topi, topw);
        zero_counts<<<1, 32>>>(cnt);
        gather_rows<<<SEQ, 256>>>(xb, xg, topi, pos, cnt);
        cudaStreamWaitEvent(0, evM[l], 0);

        moe_gemm_act_kernel<<<dim3((2 * FFI) / 128, NEXP * 16), 256, GEMM_SMEM>>>(
            xg, w + O_GU, actb, cnt);
        moe_gemm_kernel<<<dim3(DIM / 128, NEXP * 16), 256, GEMM_SMEM>>>(
            actb, w + O_DN, ygb, cnt, FFI, DIM);
        scatter_add<<<SEQ, 256>>>(h, ygb, topi, pos, topw);

        // ---- shared expert (fused act) ----
        gemm_act_kernel<<<dim3((2 * SFI) / 128, SEQ / 128), 256, GEMM_SMEM>>>(
            xb, w + O_SH, gsb, DIM);
        gemm_acc(gsb, w + O_SD, h, SEQ, DIM, SFI, SFI, SFI, DIM);
    }

    // ---- head + fused loss ----
    rmsnorm_kernel<<<SEQ, 256>>>(h, final_ln, xb);
    cudaStreamWaitEvent(0, evLM, 0);
    lmhead_gemm_loss<<<dim3(NCB, SEQ / 128), 256, GEMM_SMEM>>>(xb, wbL, partb, DIM);
    zero_scalar<<<1, 32>>>(out);
    loss_reduce<<<SEQ, 256>>>(partb, xb, wbL, tgt, out);
}

// round 16
// speedup vs baseline: 1.0015x; 1.0015x over previous
#include <cuda_runtime.h>
#include <cuda_bf16.h>
#include <math.h>
#include <stdint.h>

// Model dims
#define SEQ    2048
#define DIM    1024
#define NHEAD  16
#define DH     64
#define NLAYER 2
#define NEXP   8
#define FFI    512
#define SFI    1024
#define VOCAB  32000
#define NCB    (VOCAB / 128)

#define BK 64
#define NSTAGE 3
#define BSTRIDE 72
#define STAGE_BYTES (128 * BSTRIDE * 2)        // 18432
#define GEMM_SMEM (2 * NSTAGE * STAGE_BYTES)   // 110592

#define CONV_GRID 1184

#define QSCALE 0.1803368801111137f  // 0.125 * log2(e)

// flash-attn smem layout (bytes)
#define FA_Q     0
#define FA_QSZ   (128 * 72 * 2)
#define FA_K     (FA_Q + FA_QSZ)
#define FA_KSZ   (128 * 72 * 2)
#define FA_V     (FA_K + 2 * FA_KSZ)
#define FA_VSZ   (64 * 136 * 2)
#define FA_SMEM  (FA_V + 2 * FA_VSZ)    // 90112

// layer weight scratch layout (bf16 elems)
#define WDD   ((size_t)DIM * DIM)
#define O_QKV 0
#define O_WO  (3 * WDD)
#define O_GU  (4 * WDD)
#define O_DN  (O_GU + (size_t)NEXP * 2 * FFI * DIM)
#define O_SH  (O_DN + (size_t)NEXP * FFI * DIM)
#define O_SD  (O_SH + (size_t)2 * SFI * DIM)
#define WL_TOTAL (O_SD + (size_t)SFI * DIM)

// ---------------- static scratch ----------------
__device__ float g_h[SEQ * DIM];
__device__ __nv_bfloat16 g_xb[SEQ * DIM];
__device__ __nv_bfloat16 g_qkvb[SEQ * 3 * DIM];
__device__ __nv_bfloat16 g_qbh[(size_t)NHEAD * SEQ * DH];
__device__ __nv_bfloat16 g_kbh[(size_t)NHEAD * SEQ * DH];
__device__ __nv_bfloat16 g_vth[(size_t)NHEAD * DH * SEQ];
__device__ __nv_bfloat16 g_ob[SEQ * DIM];
__device__ __nv_bfloat16 g_ygb[(size_t)NEXP * SEQ * DIM];   // MoE down outputs (bf16)
__device__ __nv_bfloat16 g_actb[(size_t)NEXP * SEQ * FFI];
__device__ __nv_bfloat16 g_gsb[SEQ * SFI];
__device__ __nv_bfloat16 g_wl0[WL_TOTAL];
__device__ __nv_bfloat16 g_wl1[WL_TOTAL];
__device__ __nv_bfloat16 g_wbL[(size_t)VOCAB * DIM];
__device__ float2 g_part[(size_t)SEQ * NCB];
__device__ int   g_cnt[NEXP];
__device__ int   g_tmap[NEXP * SEQ];
__device__ int2  g_topi[SEQ];
__device__ int2  g_pos[SEQ];
__device__ float2 g_topw[SEQ];

// ---------------- helpers ----------------
__device__ __forceinline__ uint32_t cvt_bf16x2(float lo, float hi) {
    uint32_t r;
    asm("cvt.rn.bf16x2.f32 %0, %1, %2;" : "=r"(r) : "f"(hi), "f"(lo));
    return r;
}
__device__ __forceinline__ void ldsm4(uint32_t &r0, uint32_t &r1, uint32_t &r2, uint32_t &r3,
                                      uint32_t addr) {
    asm volatile("ldmatrix.sync.aligned.m8n8.x4.shared.b16 {%0,%1,%2,%3}, [%4];"
                 : "=r"(r0), "=r"(r1), "=r"(r2), "=r"(r3) : "r"(addr));
}
__device__ __forceinline__ void mma16816(float* c, const uint32_t* a, const uint32_t* b) {
    asm volatile(
        "mma.sync.aligned.m16n8k16.row.col.f32.bf16.bf16.f32 "
        "{%0,%1,%2,%3}, {%4,%5,%6,%7}, {%8,%9}, {%0,%1,%2,%3};"
        : "+f"(c[0]), "+f"(c[1]), "+f"(c[2]), "+f"(c[3])
        : "r"(a[0]), "r"(a[1]), "r"(a[2]), "r"(a[3]), "r"(b[0]), "r"(b[1]));
}
__device__ __forceinline__ void cp_async16(uint32_t dst, const void* src) {
    asm volatile("cp.async.cg.shared.global [%0], [%1], 16;" :: "r"(dst), "l"(src));
}
__device__ __forceinline__ void cp_commit() { asm volatile("cp.async.commit_group;"); }
template<int W> __device__ __forceinline__ void cp_wait() {
    asm volatile("cp.async.wait_group %0;" :: "n"(W));
}

// ---------------- 128x128 GEMM mainloop, per-thread row pointers ----------------
__device__ __forceinline__ void gemm128_mainloop_p(
    const __nv_bfloat16* const (&Ar)[4], const __nv_bfloat16* const (&Br)[4],
    int K, float acc[2][8][4])
{
    extern __shared__ __align__(16) __nv_bfloat16 smem[];
    const int tid = threadIdx.x;
    const int lane = tid & 31;
    const int wid = tid >> 5;
    const int warp_m = wid & 3;
    const int warp_n = wid >> 2;
    const int g = lane >> 3, lr = lane & 7;

    const uint32_t As_base = (uint32_t)__cvta_generic_to_shared(smem);
    const uint32_t Bs_base = As_base + NSTAGE * STAGE_BYTES;
    const int ntiles = K >> 6;

    auto issue = [&](int t, int s) {
        const uint32_t a_s = As_base + s * STAGE_BYTES;
        const uint32_t b_s = Bs_base + s * STAGE_BYTES;
#pragma unroll
        for (int i = 0; i < 4; i++) {
            int id = i * 256 + tid;
            int r = id >> 3;
            int c = (id & 7) * 8;
            cp_async16(a_s + (r * BSTRIDE + c) * 2, Ar[i] + t * BK + c);
            cp_async16(b_s + (r * BSTRIDE + c) * 2, Br[i] + t * BK + c);
        }
    };

#pragma unroll
    for (int s = 0; s < NSTAGE - 1; s++) {
        if (s < ntiles) issue(s, s);
        cp_commit();
    }

#pragma unroll
    for (int mt = 0; mt < 2; mt++)
#pragma unroll
        for (int nt = 0; nt < 8; nt++)
#pragma unroll
            for (int i = 0; i < 4; i++) acc[mt][nt][i] = 0.f;

    int s = 0;
    for (int t = 0; t < ntiles; t++) {
        cp_wait<NSTAGE - 2>();
        __syncthreads();

        const uint32_t a_base = As_base + s * STAGE_BYTES;
        const uint32_t b_base = Bs_base + s * STAGE_BYTES;

#pragma unroll
        for (int ks = 0; ks < 4; ks++) {
            uint32_t a[2][4];
#pragma unroll
            for (int mt = 0; mt < 2; mt++) {
                int row = warp_m * 32 + mt * 16 + (g & 1) * 8 + lr;
                int col = ks * 16 + (g >> 1) * 8;
                ldsm4(a[mt][0], a[mt][1], a[mt][2], a[mt][3],
                      a_base + (uint32_t)(row * BSTRIDE + col) * 2);
            }
            uint32_t b[8][2];
#pragma unroll
            for (int np = 0; np < 4; np++) {
                int row = warp_n * 64 + np * 16 + (g >> 1) * 8 + lr;
                int col = ks * 16 + (g & 1) * 8;
                uint32_t r0, r1, r2, r3;
                ldsm4(r0, r1, r2, r3, b_base + (uint32_t)(row * BSTRIDE + col) * 2);
                b[2 * np][0] = r0; b[2 * np][1] = r1;
                b[2 * np + 1][0] = r2; b[2 * np + 1][1] = r3;
            }
#pragma unroll
            for (int mt = 0; mt < 2; mt++)
#pragma unroll
                for (int nt = 0; nt < 8; nt++)
                    mma16816(acc[mt][nt], a[mt], b[nt]);
        }

        int nt2 = t + NSTAGE - 1;
        if (nt2 < ntiles) {
            int s2 = nt2 % NSTAGE;
            issue(nt2, s2);
        }
        cp_commit();
        s = (s + 1 == NSTAGE) ? 0 : s + 1;
    }
}

__device__ __forceinline__ void gemm128_mainloop(
    const __nv_bfloat16* __restrict__ A, const __nv_bfloat16* __restrict__ B,
    int K, int lda, int ldb, float acc[2][8][4])
{
    const int tid = threadIdx.x;
    const __nv_bfloat16* Ar[4];
    const __nv_bfloat16* Br[4];
#pragma unroll
    for (int i = 0; i < 4; i++) {
        int r = (i * 256 + tid) >> 3;
        Ar[i] = A + (size_t)r * lda;
        Br[i] = B + (size_t)r * ldb;
    }
    gemm128_mainloop_p(Ar, Br, K, acc);
}

template<bool ACC>
__device__ __forceinline__ void epilogue_store(float* __restrict__ C, int ldc,
                                               float acc[2][8][4])
{
    const int tid = threadIdx.x;
    const int lane = tid & 31;
    const int wid = tid >> 5;
    const int warp_m = wid & 3;
    const int warp_n = wid >> 2;
    const int r0c = lane >> 2;
    const int cc  = (lane & 3) * 2;
#pragma unroll
    for (int mt = 0; mt < 2; mt++) {
        int rbase = warp_m * 32 + mt * 16 + r0c;
#pragma unroll
        for (int nt = 0; nt < 8; nt++) {
            int col = warp_n * 64 + nt * 8 + cc;
            size_t i00 = (size_t)rbase * ldc + col;
            size_t i10 = (size_t)(rbase + 8) * ldc + col;
            if (ACC) {
                C[i00]     += acc[mt][nt][0]; C[i00 + 1] += acc[mt][nt][1];
                C[i10]     += acc[mt][nt][2]; C[i10 + 1] += acc[mt][nt][3];
            } else {
                C[i00]     = acc[mt][nt][0]; C[i00 + 1] = acc[mt][nt][1];
                C[i10]     = acc[mt][nt][2]; C[i10 + 1] = acc[mt][nt][3];
            }
        }
    }
}

__device__ __forceinline__ void epilogue_store_bf16(__nv_bfloat16* __restrict__ C, int ldc,
                                                    float acc[2][8][4])
{
    const int tid = threadIdx.x;
    const int lane = tid & 31;
    const int wid = tid >> 5;
    const int warp_m = wid & 3;
    const int warp_n = wid >> 2;
    const int r0c = lane >> 2;
    const int cc  = (lane & 3) * 2;
#pragma unroll
    for (int mt = 0; mt < 2; mt++) {
        int rbase = warp_m * 32 + mt * 16 + r0c;
#pragma unroll
        for (int nt = 0; nt < 8; nt++) {
            int col = warp_n * 64 + nt * 8 + cc;
            *(uint32_t*)(C + (size_t)rbase * ldc + col) =
                cvt_bf16x2(acc[mt][nt][0], acc[mt][nt][1]);
            *(uint32_t*)(C + (size_t)(rbase + 8) * ldc + col) =
                cvt_bf16x2(acc[mt][nt][2], acc[mt][nt][3]);
        }
    }
}

__device__ __forceinline__ void epilogue_act(__nv_bfloat16* __restrict__ O, int ldo,
                                             float acc[2][8][4])
{
    const int tid = threadIdx.x;
    const int lane = tid & 31;
    const int wid = tid >> 5;
    const int warp_m = wid & 3;
    const int warp_n = wid >> 2;
    const int r0c = lane >> 2;
    const int cp0 = lane & 3;
#pragma unroll
    for (int mt = 0; mt < 2; mt++) {
        int rbase = warp_m * 32 + mt * 16 + r0c;
#pragma unroll
        for (int nt = 0; nt < 8; nt++) {
            int cp = warp_n * 32 + nt * 4 + cp0;
            float g0 = acc[mt][nt][0], u0 = acc[mt][nt][1];
            float g1 = acc[mt][nt][2], u1 = acc[mt][nt][3];
            float s0 = 1.f / (1.f + expf(-g0));
            float s1 = 1.f / (1.f + expf(-g1));
            O[(size_t)rbase * ldo + cp]       = __float2bfloat16(g0 * s0 * u0);
            O[(size_t)(rbase + 8) * ldo + cp] = __float2bfloat16(g1 * s1 * u1);
        }
    }
}

template<bool ACC>
__global__ void __launch_bounds__(256, 2) bf16_gemm_kernel(
    const __nv_bfloat16* __restrict__ A, const __nv_bfloat16* __restrict__ B,
    float* __restrict__ C, int K, int lda, int ldb, int ldc)
{
    A += (size_t)blockIdx.y * 128 * lda;
    B += (size_t)blockIdx.x * 128 * ldb;
    C += (size_t)blockIdx.y * 128 * ldc + blockIdx.x * 128;
    float acc[2][8][4];
    gemm128_mainloop(A, B, K, lda, ldb, acc);
    epilogue_store<ACC>(C, ldc, acc);
}

__global__ void __launch_bounds__(256, 2) bf16_gemm_bf16out(
    const __nv_bfloat16* __restrict__ A, const __nv_bfloat16* __restrict__ B,
    __nv_bfloat16* __restrict__ C, int K, int lda, int ldb, int ldc)
{
    A += (size_t)blockIdx.y * 128 * lda;
    B += (size_t)blockIdx.x * 128 * ldb;
    C += (size_t)blockIdx.y * 128 * ldc + blockIdx.x * 128;
    float acc[2][8][4];
    gemm128_mainloop(A, B, K, lda, ldb, acc);
    epilogue_store_bf16(C, ldc, acc);
}

__global__ void __launch_bounds__(256, 2) gemm_act_kernel(
    const __nv_bfloat16* __restrict__ A, const __nv_bfloat16* __restrict__ B,
    __nv_bfloat16* __restrict__ O, int K)
{
    A += (size_t)blockIdx.y * 128 * K;
    B += (size_t)blockIdx.x * 128 * K;
    O += (size_t)blockIdx.y * 128 * SFI + blockIdx.x * 64;
    float acc[2][8][4];
    gemm128_mainloop(A, B, K, K, K, acc);
    epilogue_act(O, SFI, acc);
}

// MoE gate|up GEMM with indirect A rows (token map) + fused SiLU*up
__global__ void __launch_bounds__(256, 2) moe_gemm_act_kernel(
    const __nv_bfloat16* __restrict__ xb, const __nv_bfloat16* __restrict__ B,
    __nv_bfloat16* __restrict__ O, const int* __restrict__ cnt,
    const int* __restrict__ tmap)
{
    const int e = blockIdx.y >> 4;
    const int rb = blockIdx.y & 15;
    if (rb * 128 >= cnt[e]) return;
    const int* rmap = tmap + e * SEQ + rb * 128;
    B += (size_t)e * (2 * FFI) * DIM + (size_t)blockIdx.x * 128 * DIM;
    O += ((size_t)e * SEQ + rb * 128) * FFI + blockIdx.x * 64;

    const int tid = threadIdx.x;
    const __nv_bfloat16* Ar[4];
    const __nv_bfloat16* Br[4];
#pragma unroll
    for (int i = 0; i < 4; i++) {
        int r = (i * 256 + tid) >> 3;
        int tok = rmap[r] & (SEQ - 1);        // mask keeps stale entries in-range
        Ar[i] = xb + (size_t)tok * DIM;
        Br[i] = B + (size_t)r * DIM;
    }
    float acc[2][8][4];
    gemm128_mainloop_p(Ar, Br, DIM, acc);
    epilogue_act(O, FFI, acc);
}

// MoE down GEMM, bf16 output
__global__ void __launch_bounds__(256, 2) moe_gemm_kernel(
    const __nv_bfloat16* __restrict__ A, const __nv_bfloat16* __restrict__ B,
    __nv_bfloat16* __restrict__ C, const int* __restrict__ cnt, int K, int N)
{
    const int e = blockIdx.y >> 4;
    const int rb = blockIdx.y & 15;
    if (rb * 128 >= cnt[e]) return;
    A += ((size_t)e * SEQ + rb * 128) * K;
    B += (size_t)e * N * K + (size_t)blockIdx.x * 128 * K;
    C += ((size_t)e * SEQ + rb * 128) * N + blockIdx.x * 128;
    float acc[2][8][4];
    gemm128_mainloop(A, B, K, K, K, acc);
    epilogue_store_bf16(C, N, acc);
}

__global__ void __launch_bounds__(256, 2) lmhead_gemm_loss(
    const __nv_bfloat16* __restrict__ A, const __nv_bfloat16* __restrict__ B,
    float2* __restrict__ part, int K)
{
    const int bx = blockIdx.x;
    A += (size_t)blockIdx.y * 128 * K;
    B += (size_t)bx * 128 * K;
    float acc[2][8][4];
    gemm128_mainloop(A, B, K, K, K, acc);

    const int tid = threadIdx.x;
    const int lane = tid & 31;
    const int wid = tid >> 5;
    const int warp_m = wid & 3;
    const int warp_n = wid >> 2;

    __shared__ float sm_m[2][128], sm_s[2][128];

#pragma unroll
    for (int mt = 0; mt < 2; mt++) {
#pragma unroll
        for (int half = 0; half < 2; half++) {
            float m = -1e30f;
#pragma unroll
            for (int nt = 0; nt < 8; nt++)
                m = fmaxf(m, fmaxf(acc[mt][nt][2 * half], acc[mt][nt][2 * half + 1]));
            m = fmaxf(m, __shfl_xor_sync(0xffffffffu, m, 1));
            m = fmaxf(m, __shfl_xor_sync(0xffffffffu, m, 2));
            float s = 0.f;
#pragma unroll
            for (int nt = 0; nt < 8; nt++)
                s += expf(acc[mt][nt][2 * half] - m) + expf(acc[mt][nt][2 * half + 1] - m);
            s += __shfl_xor_sync(0xffffffffu, s, 1);
            s += __shfl_xor_sync(0xffffffffu, s, 2);
            if ((lane & 3) == 0) {
                int row_local = warp_m * 32 + mt * 16 + half * 8 + (lane >> 2);
                sm_m[warp_n][row_local] = m;
                sm_s[warp_n][row_local] = s;
            }
        }
    }
    __syncthreads();

    if (tid < 128) {
        float m1 = sm_m[0][tid], s1 = sm_s[0][tid];
        float m2 = sm_m[1][tid], s2 = sm_s[1][tid];
        float nm = fmaxf(m1, m2);
        float ns = s1 * expf(m1 - nm) + s2 * expf(m2 - nm);
        int row = blockIdx.y * 128 + tid;
        part[(size_t)row * NCB + bx] = make_float2(nm, ns);
    }
}

__global__ void loss_reduce(const float2* __restrict__ part,
                            const __nv_bfloat16* __restrict__ xb,
                            const __nv_bfloat16* __restrict__ wb,
                            const int* __restrict__ tgt, float* __restrict__ out)
{
    int row = blockIdx.x;
    int tid = threadIdx.x;

    float m = -1e30f, s = 0.f;
    for (int j = tid; j < NCB; j += 256) {
        float2 p = part[(size_t)row * NCB + j];
        float nm = fmaxf(m, p.x);
        s = s * expf(m - nm) + p.y * expf(p.x - nm);
        m = nm;
    }

    __shared__ float ms[256], ss[256], ds[256];
    ms[tid] = m; ss[tid] = s;
    __syncthreads();
    for (int st = 128; st > 0; st >>= 1) {
        if (tid < st) {
            float m1 = ms[tid], m2 = ms[tid + st];
            float nm = fmaxf(m1, m2);
            ss[tid] = ss[tid] * expf(m1 - nm) + ss[tid + st] * expf(m2 - nm);
            ms[tid] = nm;
        }
        __syncthreads();
    }

    int lab = tgt[row];
    int slab = (lab == -100) ? 0 : lab;
    const __nv_bfloat16* xr = xb + (size_t)row * DIM;
    const __nv_bfloat16* wr = wb + (size_t)slab * DIM;
    float d = 0.f;
    for (int i = tid; i < DIM; i += 256)
        d += __bfloat162float(xr[i]) * __bfloat162float(wr[i]);
    ds[tid] = d;
    __syncthreads();
    for (int st = 128; st > 0; st >>= 1) {
        if (tid < st) ds[tid] += ds[tid + st];
        __syncthreads();
    }

    if (tid == 0 && lab != -100) {
        float lse = ms[0] + logf(ss[0]);
        atomicAdd(out, lse - ds[0]);
    }
}

// ---------------- weight conversion (grid-stride) ----------------
__global__ void convert_w(const float* __restrict__ w, __nv_bfloat16* __restrict__ wb,
                          size_t n4)
{
    const float4* w4 = (const float4*)w;
    uint2* o2 = (uint2*)wb;
    size_t stride = (size_t)gridDim.x * 256;
    for (size_t i = (size_t)blockIdx.x * 256 + threadIdx.x; i < n4; i += stride * 4) {
        float4 v[4];
        bool ok[4];
#pragma unroll
        for (int k = 0; k < 4; k++) {
            size_t j = i + (size_t)k * stride;
            ok[k] = j < n4;
            if (ok[k]) v[k] = w4[j];
        }
#pragma unroll
        for (int k = 0; k < 4; k++) if (ok[k]) {
            uint2 pk;
            pk.x = cvt_bf16x2(v[k].x, v[k].y);
            pk.y = cvt_bf16x2(v[k].z, v[k].w);
            o2[i + (size_t)k * stride] = pk;
        }
    }
}

__global__ void convert_pair(const float* __restrict__ a, const float* __restrict__ b,
                             __nv_bfloat16* __restrict__ wb, size_t n4, int log2r2)
{
    uint2* o2 = (uint2*)wb;
    size_t stride = (size_t)gridDim.x * 256;
    for (size_t i = (size_t)blockIdx.x * 256 + threadIdx.x; i < n4; i += stride * 4) {
        float4 v[4];
        bool ok[4];
#pragma unroll
        for (int k = 0; k < 4; k++) {
            size_t j = i + (size_t)k * stride;
            ok[k] = j < n4;
            if (ok[k]) {
                int k4 = (int)(j & 255);
                size_t n = j >> 8;
                size_t e = n >> log2r2;
                int r = (int)(n & ((1u << log2r2) - 1));
                const float* src = ((r & 1) ? b : a)
                    + ((e << (log2r2 - 1)) + (r >> 1)) * (size_t)DIM + k4 * 4;
                v[k] = *(const float4*)src;
            }
        }
#pragma unroll
        for (int k = 0; k < 4; k++) if (ok[k]) {
            uint2 pk;
            pk.x = cvt_bf16x2(v[k].x, v[k].y);
            pk.y = cvt_bf16x2(v[k].z, v[k].w);
            o2[i + (size_t)k * stride] = pk;
        }
    }
}

// ---------------- rope (bf16 in) -> bf16 per-head Q/K ----------------
__global__ void rope_bf16_kernel(const __nv_bfloat16* __restrict__ qkv,
                                 __nv_bfloat16* __restrict__ qb,
                                 __nv_bfloat16* __restrict__ kb)
{
    int s = blockIdx.x;
    int tid = threadIdx.x;
    int h = tid >> 5, i = tid & 31;
    float freq = powf(10000.f, -(float)(2 * i) / 64.f);
    float ang = (float)s * freq;
    float sn, cs;
    sincosf(ang, &sn, &cs);
    size_t src = (size_t)s * (3 * DIM) + h * DH + i;
    float q1 = __bfloat162float(qkv[src]), q2 = __bfloat162float(qkv[src + 32]);
    size_t dst = ((size_t)h * SEQ + s) * DH + i;
    qb[dst]      = __float2bfloat16((q1 * cs - q2 * sn) * QSCALE);
    qb[dst + 32] = __float2bfloat16((q2 * cs + q1 * sn) * QSCALE);
    float k1 = __bfloat162float(qkv[src + DIM]), k2 = __bfloat162float(qkv[src + DIM + 32]);
    kb[dst]      = __float2bfloat16(k1 * cs - k2 * sn);
    kb[dst + 32] = __float2bfloat16(k2 * cs + k1 * sn);
}

__global__ void vtrans_kernel(const __nv_bfloat16* __restrict__ v,
                              __nv_bfloat16* __restrict__ vt)
{
    __shared__ __nv_bfloat16 tile[32][34];
    int s0 = blockIdx.x * 32, d0 = blockIdx.y * 32;
    int tx = threadIdx.x, ty = threadIdx.y;
#pragma unroll
    for (int i = 0; i < 4; i++) {
        int row = ty + i * 8;
        tile[row][tx] = v[(size_t)(s0 + row) * (3 * DIM) + 2 * DIM + d0 + tx];
    }
    __syncthreads();
#pragma unroll
    for (int i = 0; i < 4; i++) {
        int row = ty + i * 8;
        vt[(size_t)(d0 + row) * SEQ + s0 + tx] = tile[tx][row];
    }
}

// ---------------- flash attention (longest-first scheduling) ----------------
__global__ void __launch_bounds__(256, 1) flash_attn2_kernel(
    const __nv_bfloat16* __restrict__ qb, const __nv_bfloat16* __restrict__ kb,
    const __nv_bfloat16* __restrict__ vt, __nv_bfloat16* __restrict__ ob)
{
    extern __shared__ __align__(16) char fasm[];
    const int qblk = (int)gridDim.x - 1 - (int)blockIdx.x;   // longest jobs first
    const int head = blockIdx.y;
    const int q0 = qblk * 128;

    const int tid = threadIdx.x;
    const int lane = tid & 31;
    const int wid = tid >> 5;
    const int g = lane >> 3, lr = lane & 7;
    const int r0 = wid * 16;

    const uint32_t smb = (uint32_t)__cvta_generic_to_shared(fasm);
    const uint32_t Qs = smb + FA_Q;
    const uint32_t Ks = smb + FA_K;
    const uint32_t Vs = smb + FA_V;

    const __nv_bfloat16* Qg = qb + ((size_t)head * SEQ + q0) * DH;
    const __nv_bfloat16* Kg = kb + (size_t)head * SEQ * DH;
    const __nv_bfloat16* Vg = vt + (size_t)head * DH * SEQ;

#pragma unroll
    for (int i = 0; i < 4; i++) {
        int id = i * 256 + tid;
        int r = id >> 3;
        int c = id & 7;
        cp_async16(Qs + (uint32_t)(r * 144 + c * 16), Qg + (size_t)r * DH + c * 8);
    }
    cp_commit();

    auto issueKV = [&](int kblk, int buf) {
        const int kk0 = kblk * 128;
        const uint32_t kdst = Ks + buf * FA_KSZ;
        const uint32_t vdst = Vs + buf * FA_VSZ;
#pragma unroll
        for (int i = 0; i < 4; i++) {
            int id = i * 256 + tid;
            int r = id >> 3;
            int c = id & 7;
            cp_async16(kdst + (uint32_t)(r * 144 + c * 16),
                       Kg + (size_t)(kk0 + r) * DH + c * 8);
        }
#pragma unroll
        for (int i = 0; i < 4; i++) {
            int id = i * 256 + tid;
            int d = id >> 4;
            int c = id & 15;
            cp_async16(vdst + (uint32_t)(d * 272 + c * 16),
                       Vg + (size_t)d * SEQ + kk0 + c * 8);
        }
    };

    issueKV(0, 0);
    cp_commit();
    cp_wait<0>();
    __syncthreads();

    uint32_t qa[4][4];
#pragma unroll
    for (int kt = 0; kt < 4; kt++) {
        int row = r0 + (g & 1) * 8 + lr;
        int col = kt * 16 + (g >> 1) * 8;
        ldsm4(qa[kt][0], qa[kt][1], qa[kt][2], qa[kt][3],
              Qs + (uint32_t)(row * 72 + col) * 2);
    }

    float acc_o[8][4];
#pragma unroll
    for (int nt = 0; nt < 8; nt++)
#pragma unroll
        for (int i = 0; i < 4; i++) acc_o[nt][i] = 0.f;

    float mA = -1e30f, mB = -1e30f, lA = 0.f, lB = 0.f;
    const int rA = q0 + r0 + (lane >> 2);
    const int rB = rA + 8;

    for (int kblk = 0; kblk <= qblk; kblk++) {
        const int kk0 = kblk * 128;
        const int buf = kblk & 1;

        if (kblk > 0) {
            cp_wait<0>();
            __syncthreads();
        }
        if (kblk < qblk) {
            issueKV(kblk + 1, buf ^ 1);
            cp_commit();
        }

        const uint32_t kbase = Ks + buf * FA_KSZ;
        const uint32_t vbase = Vs + buf * FA_VSZ;

        float sacc[16][4];
#pragma unroll
        for (int nt = 0; nt < 16; nt++)
#pragma unroll
            for (int i = 0; i < 4; i++) sacc[nt][i] = 0.f;

#pragma unroll
        for (int kt = 0; kt < 4; kt++) {
#pragma unroll
            for (int np = 0; np < 8; np++) {
                int row = np * 16 + (g >> 1) * 8 + lr;
                int col = kt * 16 + (g & 1) * 8;
                uint32_t b0, b1, b2, b3;
                ldsm4(b0, b1, b2, b3, kbase + (uint32_t)(row * 72 + col) * 2);
                uint32_t bb0[2] = {b0, b1}, bb1[2] = {b2, b3};
                mma16816(sacc[2 * np],     qa[kt], bb0);
                mma16816(sacc[2 * np + 1], qa[kt], bb1);
            }
        }

        if (kblk == qblk) {
#pragma unroll
            for (int nt = 0; nt < 16; nt++) {
                int cb = kk0 + nt * 8 + 2 * (lane & 3);
                if (cb     > rA) sacc[nt][0] = -1e30f;
                if (cb + 1 > rA) sacc[nt][1] = -1e30f;
                if (cb     > rB) sacc[nt][2] = -1e30f;
                if (cb + 1 > rB) sacc[nt][3] = -1e30f;
            }
        }

        float cmA = -1e30f, cmB = -1e30f;
#pragma unroll
        for (int nt = 0; nt < 16; nt++) {
            cmA = fmaxf(cmA, fmaxf(sacc[nt][0], sacc[nt][1]));
            cmB = fmaxf(cmB, fmaxf(sacc[nt][2], sacc[nt][3]));
        }
        cmA = fmaxf(cmA, __shfl_xor_sync(0xffffffffu, cmA, 1));
        cmA = fmaxf(cmA, __shfl_xor_sync(0xffffffffu, cmA, 2));
        cmB = fmaxf(cmB, __shfl_xor_sync(0xffffffffu, cmB, 1));
        cmB = fmaxf(cmB, __shfl_xor_sync(0xffffffffu, cmB, 2));

        float nmA = fmaxf(mA, cmA), nmB = fmaxf(mB, cmB);
        float scA = exp2f(mA - nmA), scB = exp2f(mB - nmB);
        mA = nmA; mB = nmB;

        uint32_t pA[16], pB[16];
        float sA = 0.f, sB = 0.f;
#pragma unroll
        for (int nt = 0; nt < 16; nt++) {
            float p0 = exp2f(sacc[nt][0] - mA);
            float p1 = exp2f(sacc[nt][1] - mA);
            float p2 = exp2f(sacc[nt][2] - mB);
            float p3 = exp2f(sacc[nt][3] - mB);
            sA += p0 + p1; sB += p2 + p3;
            pA[nt] = cvt_bf16x2(p0, p1);
            pB[nt] = cvt_bf16x2(p2, p3);
        }
        lA = lA * scA + sA;
        lB = lB * scB + sB;
#pragma unroll
        for (int nt = 0; nt < 8; nt++) {
            acc_o[nt][0] *= scA; acc_o[nt][1] *= scA;
            acc_o[nt][2] *= scB; acc_o[nt][3] *= scB;
        }

#pragma unroll
        for (int kt2 = 0; kt2 < 8; kt2++) {
            uint32_t a[4] = { pA[2 * kt2], pB[2 * kt2], pA[2 * kt2 + 1], pB[2 * kt2 + 1] };
#pragma unroll
            for (int np2 = 0; np2 < 4; np2++) {
                int row = np2 * 16 + (g >> 1) * 8 + lr;
                int col = kt2 * 16 + (g & 1) * 8;
                uint32_t b0, b1, b2, b3;
                ldsm4(b0, b1, b2, b3, vbase + (uint32_t)(row * 136 + col) * 2);
                uint32_t bb0[2] = {b0, b1}, bb1[2] = {b2, b3};
                mma16816(acc_o[2 * np2],     a, bb0);
                mma16816(acc_o[2 * np2 + 1], a, bb1);
            }
        }
    }

    lA += __shfl_xor_sync(0xffffffffu, lA, 1);
    lA += __shfl_xor_sync(0xffffffffu, lA, 2);
    lB += __shfl_xor_sync(0xffffffffu, lB, 1);
    lB += __shfl_xor_sync(0xffffffffu, lB, 2);
    float iA = 1.f / lA, iB = 1.f / lB;

#pragma unroll
    for (int nt = 0; nt < 8; nt++) {
        int col = head * DH + nt * 8 + 2 * (lane & 3);
        uint32_t p0 = cvt_bf16x2(acc_o[nt][0] * iA, acc_o[nt][1] * iA);
        uint32_t p1 = cvt_bf16x2(acc_o[nt][2] * iB, acc_o[nt][3] * iB);
        *(uint32_t*)(ob + (size_t)rA * DIM + col) = p0;
        *(uint32_t*)(ob + (size_t)rB * DIM + col) = p1;
    }
}

// ---------------- small kernels ----------------
__global__ void embed_gather(const int* __restrict__ tok, const float* __restrict__ emb,
                             float* __restrict__ h)
{
    int s = blockIdx.x;
    int t = tok[s];
    const float* e = emb + (size_t)t * DIM;
    for (int d = threadIdx.x; d < DIM; d += blockDim.x)
        h[(size_t)s * DIM + d] = e[d];
}

__global__ void rmsnorm_kernel(const float* __restrict__ x, const float* __restrict__ w,
                               __nv_bfloat16* __restrict__ o)
{
    int row = blockIdx.x;
    const float* xr = x + (size_t)row * DIM;
    __shared__ float red[256];
    int tid = threadIdx.x;
    float s = 0.f;
    for (int d = tid; d < DIM; d += 256) { float v = xr[d]; s += v * v; }
    red[tid] = s; __syncthreads();
    for (int st = 128; st > 0; st >>= 1) {
        if (tid < st) red[tid] += red[tid + st];
        __syncthreads();
    }
    float rs = rsqrtf(red[0] / (float)DIM + 1e-6f);
    for (int d = tid; d < DIM; d += 256)
        o[(size_t)row * DIM + d] = __float2bfloat16(xr[d] * rs * w[d]);
}

__global__ void gate_topk(const __nv_bfloat16* __restrict__ x, const float* __restrict__ gw,
                          int2* __restrict__ topi, float2* __restrict__ topw)
{
    int t = blockIdx.x;
    int tid = threadIdx.x;
    int e = tid >> 5, lane = tid & 31;
    const __nv_bfloat16* xr = x + (size_t)t * DIM;
    const float* wr = gw + (size_t)e * DIM;
    float s = 0.f;
    for (int d = lane; d < DIM; d += 32) s += __bfloat162float(xr[d]) * wr[d];
    for (int o = 16; o; o >>= 1) s += __shfl_down_sync(0xffffffffu, s, o);
    __shared__ float lg[NEXP];
    if (lane == 0) lg[e] = s;
    __syncthreads();
    if (tid == 0) {
        float m = -1e30f;
        for (int i = 0; i < NEXP; i++) m = fmaxf(m, lg[i]);
        float p[NEXP]; float sum = 0.f;
        for (int i = 0; i < NEXP; i++) { p[i] = expf(lg[i] - m); sum += p[i]; }
        float inv = 1.f / sum;
        for (int i = 0; i < NEXP; i++) p[i] *= inv;
        int i0 = 0;
        for (int i = 1; i < NEXP; i++) if (p[i] > p[i0]) i0 = i;
        int i1 = -1;
        for (int i = 0; i < NEXP; i++) {
            if (i == i0) continue;
            if (i1 < 0 || p[i] > p[i1]) i1 = i;
        }
        topi[t] = make_int2(i0, i1);
        topw[t] = make_float2(p[i0], p[i1]);
    }
}

__global__ void zero_counts(int* cnt)
{
    if (threadIdx.x < NEXP) cnt[threadIdx.x] = 0;
}

// build per-expert token map + slots (replaces data gather)
__global__ void build_map(const int2* __restrict__ topi, int2* __restrict__ pos,
                          int* __restrict__ cnt, int* __restrict__ tmap)
{
    int t = blockIdx.x * 256 + threadIdx.x;
    if (t >= SEQ) return;
    int2 ti = topi[t];
    int s0 = atomicAdd(&cnt[ti.x], 1);
    int s1 = atomicAdd(&cnt[ti.y], 1);
    tmap[ti.x * SEQ + s0] = t;
    tmap[ti.y * SEQ + s1] = t;
    pos[t] = make_int2(s0, s1);
}

// scatter from bf16 yg
__global__ void scatter_add(float* __restrict__ h, const __nv_bfloat16* __restrict__ yg,
                            const int2* __restrict__ topi, const int2* __restrict__ pos,
                            const float2* __restrict__ topw)
{
    int t = blockIdx.x;
    int2 ti = topi[t];
    int2 ps = pos[t];
    float2 w = topw[t];
    const __nv_bfloat16* y0 = yg + ((size_t)ti.x * SEQ + ps.x) * DIM;
    const __nv_bfloat16* y1 = yg + ((size_t)ti.y * SEQ + ps.y) * DIM;
    float* hr = h + (size_t)t * DIM;
    for (int d = threadIdx.x; d < DIM; d += 256)
        hr[d] += w.x * __bfloat162float(y0[d]) + w.y * __bfloat162float(y1[d]);
}

__global__ void zero_scalar(float* p)
{
    if (threadIdx.x == 0 && blockIdx.x == 0) p[0] = 0.f;
}

// ---------------- host ----------------
static void gemm_acc(const __nv_bfloat16* A, const __nv_bfloat16* B, float* C,
                     int M, int N, int K, int lda, int ldb, int ldc)
{
    bf16_gemm_kernel<true><<<dim3(N / 128, M / 128), 256, GEMM_SMEM>>>(A, B, C, K, lda, ldb, ldc);
}
static void conv_w_s(cudaStream_t s, const float* w, __nv_bfloat16* wb, size_t nelem)
{
    convert_w<<<CONV_GRID, 256, 0, s>>>(w, wb, nelem / 4);
}

extern "C" void kernel_launch(void* const* d_in, const int* in_sizes, int n_in,
                              void* d_out, int out_size)
{
    (void)in_sizes; (void)n_in; (void)out_size;
    const int*   src       = (const int*)d_in[0];
    const int*   tgt       = (const int*)d_in[1];
    const float* embed     = (const float*)d_in[2];
    const float* Wq        = (const float*)d_in[3];
    const float* Wk        = (const float*)d_in[4];
    const float* Wv        = (const float*)d_in[5];
    const float* Wo        = (const float*)d_in[6];
    const float* ln1       = (const float*)d_in[7];
    const float* ln2       = (const float*)d_in[8];
    const float* gate_w    = (const float*)d_in[9];
    const float* gate_proj = (const float*)d_in[10];
    const float* up_proj   = (const float*)d_in[11];
    const float* down_proj = (const float*)d_in[12];
    const float* sg        = (const float*)d_in[13];
    const float* su        = (const float*)d_in[14];
    const float* sd        = (const float*)d_in[15];
    const float* final_ln  = (const float*)d_in[16];
    const float* lm_head   = (const float*)d_in[17];
    float* out = (float*)d_out;

    static cudaStream_t sC = nullptr;
    static cudaEvent_t evFork = nullptr, evA[NLAYER], evM[NLAYER], evLM = nullptr;
    if (!sC) {
        cudaStreamCreateWithFlags(&sC, cudaStreamNonBlocking);
        cudaEventCreateWithFlags(&evFork, cudaEventDisableTiming);
        for (int l = 0; l < NLAYER; l++) {
            cudaEventCreateWithFlags(&evA[l], cudaEventDisableTiming);
            cudaEventCreateWithFlags(&evM[l], cudaEventDisableTiming);
        }
        cudaEventCreateWithFlags(&evLM, cudaEventDisableTiming);

        cudaFuncSetAttribute(bf16_gemm_kernel<false>, cudaFuncAttributeMaxDynamicSharedMemorySize, GEMM_SMEM);
        cudaFuncSetAttribute(bf16_gemm_kernel<true>,  cudaFuncAttributeMaxDynamicSharedMemorySize, GEMM_SMEM);
        cudaFuncSetAttribute(bf16_gemm_bf16out,       cudaFuncAttributeMaxDynamicSharedMemorySize, GEMM_SMEM);
        cudaFuncSetAttribute(moe_gemm_kernel,         cudaFuncAttributeMaxDynamicSharedMemorySize, GEMM_SMEM);
        cudaFuncSetAttribute(moe_gemm_act_kernel,     cudaFuncAttributeMaxDynamicSharedMemorySize, GEMM_SMEM);
        cudaFuncSetAttribute(gemm_act_kernel,         cudaFuncAttributeMaxDynamicSharedMemorySize, GEMM_SMEM);
        cudaFuncSetAttribute(lmhead_gemm_loss,        cudaFuncAttributeMaxDynamicSharedMemorySize, GEMM_SMEM);
        cudaFuncSetAttribute(flash_attn2_kernel,      cudaFuncAttributeMaxDynamicSharedMemorySize, FA_SMEM);
    }

    float *h;
    __nv_bfloat16 *xb, *qkvb, *qbh, *kbh, *vth, *ob, *ygb, *actb, *gsb, *wbL;
    __nv_bfloat16 *wl[NLAYER];
    float2 *partb;
    int *cnt, *tmap; int2 *topi, *pos; float2 *topw;
    cudaGetSymbolAddress((void**)&h,     g_h);
    cudaGetSymbolAddress((void**)&xb,    g_xb);
    cudaGetSymbolAddress((void**)&qkvb,  g_qkvb);
    cudaGetSymbolAddress((void**)&qbh,   g_qbh);
    cudaGetSymbolAddress((void**)&kbh,   g_kbh);
    cudaGetSymbolAddress((void**)&vth,   g_vth);
    cudaGetSymbolAddress((void**)&ob,    g_ob);
    cudaGetSymbolAddress((void**)&ygb,   g_ygb);
    cudaGetSymbolAddress((void**)&actb,  g_actb);
    cudaGetSymbolAddress((void**)&gsb,   g_gsb);
    cudaGetSymbolAddress((void**)&wl[0], g_wl0);
    cudaGetSymbolAddress((void**)&wl[1], g_wl1);
    cudaGetSymbolAddress((void**)&wbL,   g_wbL);
    cudaGetSymbolAddress((void**)&partb, g_part);
    cudaGetSymbolAddress((void**)&cnt,   g_cnt);
    cudaGetSymbolAddress((void**)&tmap,  g_tmap);
    cudaGetSymbolAddress((void**)&topi,  g_topi);
    cudaGetSymbolAddress((void**)&pos,   g_pos);
    cudaGetSymbolAddress((void**)&topw,  g_topw);

    const size_t DD = WDD;
    const size_t EID = (size_t)NEXP * FFI * DIM;
    const size_t SD = (size_t)SFI * DIM;

    // ---- fork: weight conversions on side stream ----
    cudaEventRecord(evFork, 0);
    cudaStreamWaitEvent(sC, evFork, 0);
    for (int l = 0; l < NLAYER; l++) {
        __nv_bfloat16* wl_ = wl[l];
        conv_w_s(sC, Wq + l * DD, wl_ + O_QKV,          DD);
        conv_w_s(sC, Wk + l * DD, wl_ + O_QKV + DD,     DD);
        conv_w_s(sC, Wv + l * DD, wl_ + O_QKV + 2 * DD, DD);
        conv_w_s(sC, Wo + l * DD, wl_ + O_WO, DD);
        cudaEventRecord(evA[l], sC);
        convert_pair<<<CONV_GRID, 256, 0, sC>>>(gate_proj + l * EID, up_proj + l * EID,
                                                wl_ + O_GU, 2 * EID / 4, 10);
        conv_w_s(sC, down_proj + l * EID, wl_ + O_DN, EID);
        convert_pair<<<CONV_GRID, 256, 0, sC>>>(sg + l * SD, su + l * SD,
                                                wl_ + O_SH, 2 * SD / 4, 11);
        conv_w_s(sC, sd + l * SD, wl_ + O_SD, SD);
        cudaEventRecord(evM[l], sC);
    }
    conv_w_s(sC, lm_head, wbL, (size_t)VOCAB * DIM);
    cudaEventRecord(evLM, sC);

    // ---- main stream compute ----
    embed_gather<<<SEQ, 256>>>(src, embed, h);

    for (int l = 0; l < NLAYER; l++) {
        __nv_bfloat16* w = wl[l];
        rmsnorm_kernel<<<SEQ, 256>>>(h, ln1 + (size_t)l * DIM, xb);
        cudaStreamWaitEvent(0, evA[l], 0);

        bf16_gemm_bf16out<<<dim3((3 * DIM) / 128, SEQ / 128), 256, GEMM_SMEM>>>(
            xb, w + O_QKV, qkvb, DIM, DIM, DIM, 3 * DIM);
        rope_bf16_kernel<<<SEQ, NHEAD * 32>>>(qkvb, qbh, kbh);
        vtrans_kernel<<<dim3(SEQ / 32, DIM / 32), dim3(32, 8)>>>(qkvb, vth);

        flash_attn2_kernel<<<dim3(SEQ / 128, NHEAD), 256, FA_SMEM>>>(qbh, kbh, vth, ob);

        gemm_acc(ob, w + O_WO, h, SEQ, DIM, DIM, DIM, DIM, DIM);

        // ---- MoE (sparse top-2, indirect gather, fused act) ----
        rmsnorm_kernel<<<SEQ, 256>>>(h, ln2 + (size_t)l * DIM, xb);
        gate_topk<<<SEQ, 256>>>(xb, gate_w + (size_t)l * NEXP * DIM, topi, topw);
        zero_counts<<<1, 32>>>(cnt);
        build_map<<<SEQ / 256, 256>>>(topi, pos, cnt, tmap);
        cudaStreamWaitEvent(0, evM[l], 0);

        moe_gemm_act_kernel<<<dim3((2 * FFI) / 128, NEXP * 16), 256, GEMM_SMEM>>>(
            xb, w + O_GU, actb, cnt, tmap);
        moe_gemm_kernel<<<dim3(DIM / 128, NEXP * 16), 256, GEMM_SMEM>>>(
            actb, w + O_DN, ygb, cnt, FFI, DIM);
        scatter_add<<<SEQ, 256>>>(h, ygb, topi, pos, topw);

        // ---- shared expert (fused act) ----
        gemm_act_kernel<<<dim3((2 * SFI) / 128, SEQ / 128), 256, GEMM_SMEM>>>(
            xb, w + O_SH, gsb, DIM);
        gemm_acc(gsb, w + O_SD, h, SEQ, DIM, SFI, SFI, SFI, DIM);
    }

    // ---- head + fused loss ----
    rmsnorm_kernel<<<SEQ, 256>>>(h, final_ln, xb);
    cudaStreamWaitEvent(0, evLM, 0);
    lmhead_gemm_loss<<<dim3(NCB, SEQ / 128), 256, GEMM_SMEM>>>(xb, wbL, partb, DIM);
    zero_scalar<<<1, 32>>>(out);
    loss_reduce<<<SEQ, 256>>>(partb, xb, wbL, tgt, out);
}